// round 5
// baseline (speedup 1.0000x reference)
#include <cuda_runtime.h>

#define NTB 512            // tiles in a 16384-point DB (32 pts/tile)
#define NTA 32             // tiles in a 1024-point DB

// scratch (device globals; no allocation)
__device__ float4 g_Bs[24][16384];   // sorted gt/tgt: {x,y,z, 0.5*|p|^2}
__device__ float4 g_As[24][1024];    // sorted sp/tsp
__device__ float  g_acc[4];          // [0]=p1 ch1, [1]=p1 ch2, [2]=p2 ch1, [3]=p2 ch2

__device__ __forceinline__ unsigned int sortable(float x) {
    unsigned int u = __float_as_uint(x);
    return (u & 0x80000000u) ? ~u : (u | 0x80000000u);
}
__device__ __forceinline__ float warp_max_f(float v) {   // v >= 0
    return __int_as_float(__reduce_max_sync(0xffffffffu, __float_as_int(v)));
}

// ---------------- sort: one block per array, bitonic on (sortable(x)<<32 | idx)
__global__ __launch_bounds__(1024)
void k_sort(const float* __restrict__ gt, const float* __restrict__ sp,
            const float* __restrict__ tgt, const float* __restrict__ tsp)
{
    extern __shared__ unsigned long long sk[];
    int job = blockIdx.x;
    int n; const float* src; float4* dst;
    if (job < 24) {
        n = 16384;
        src = (job < 8) ? gt + (size_t)job * 16384 * 3
                        : tgt + (size_t)(job - 8) * 16384 * 3;
        dst = g_Bs[job];
    } else {
        int j = job - 24;
        n = 1024;
        src = (j < 8) ? sp + (size_t)j * 1024 * 3
                      : tsp + (size_t)(j - 8) * 1024 * 3;
        dst = g_As[j];
    }
    int tid = threadIdx.x;
    for (int i = tid; i < n; i += 1024) {
        unsigned int u = sortable(src[(size_t)i * 3]);
        sk[i] = ((unsigned long long)u << 32) | (unsigned int)i;
    }
    __syncthreads();
    for (int k = 2; k <= n; k <<= 1) {
        for (int j = k >> 1; j > 0; j >>= 1) {
            for (int i = tid; i < n; i += 1024) {
                int ixj = i ^ j;
                if (ixj > i) {
                    unsigned long long a = sk[i], b = sk[ixj];
                    bool asc = ((i & k) == 0);
                    if ((a > b) == asc) { sk[i] = b; sk[ixj] = a; }
                }
            }
            __syncthreads();
        }
    }
    for (int i = tid; i < n; i += 1024) {
        int idx = (int)(sk[i] & 0xffffffffu);
        float x = src[(size_t)idx * 3 + 0];
        float y = src[(size_t)idx * 3 + 1];
        float z = src[(size_t)idx * 3 + 2];
        dst[i] = make_float4(x, y, z, 0.5f * (x * x + y * y + z * z));
    }
}

// ---------------- NN: blocks [0,192) = pass1 (A->B), [192,3264) = pass2 (B->A)
__global__ __launch_bounds__(128)
void k_nn()
{
    __shared__ float4 sdb[1024];   // pass2: whole DB; pass1: per-warp 32-slot tiles
    const int bx = blockIdx.x;
    const int tid = threadIdx.x, lane = tid & 31, warp = tid >> 5;
    const float INF = __int_as_float(0x7f800000);

    if (bx < 192) {
        // ---- pass1: queries = sorted A rows (1024/job), DB = sorted B (16384)
        const int job = bx >> 3;
        const int wg  = ((bx & 7) << 2) + warp;            // 0..31
        float4 A = g_As[job][wg * 32 + lane];
        const float nax = -A.x, nay = -A.y, naz = -A.z, ha = A.w;
        const float xmin = __shfl_sync(0xffffffffu, A.x, 0);
        const float xmax = __shfl_sync(0xffffffffu, A.x, 31);
        const float xq   = __shfl_sync(0xffffffffu, A.x, 16);
        const float4* __restrict__ Bp = g_Bs[job];

        int lo = 0, hi = 16384;
        while (lo < hi) { int mid = (lo + hi) >> 1; if (Bp[mid].x < xq) lo = mid + 1; else hi = mid; }
        int s0 = min(lo >> 5, NTB - 1);

        float m0 = INF, m1 = INF, m2 = INF, m3 = INF, Mq = INF;
        int tr = s0, tl = s0 - 1;
        bool canR = true, canL = (tl >= 0);
        float4* tile = sdb + warp * 32;

        while (canR || canL) {
            float gapR = INF, gapL = INF;
            if (canR) { gapR = fmaxf(Bp[tr * 32].x - xmax, 0.0f);
                        if (0.5f * gapR * gapR >= Mq) canR = false; }
            if (canL) { gapL = fmaxf(xmin - Bp[tl * 32 + 31].x, 0.0f);
                        if (0.5f * gapL * gapL >= Mq) canL = false; }
            int t;
            if (canR && (!canL || gapR <= gapL)) { t = tr++; canR = (tr < NTB); }
            else if (canL)                        { t = tl--; canL = (tl >= 0); }
            else break;

            tile[lane] = Bp[t * 32 + lane];
            __syncwarp();
#pragma unroll
            for (int j = 0; j < 32; j += 4) {
                float4 p;
                p = tile[j+0]; m0 = fminf(m0, fmaf(nax, p.x, fmaf(nay, p.y, fmaf(naz, p.z, p.w))));
                p = tile[j+1]; m1 = fminf(m1, fmaf(nax, p.x, fmaf(nay, p.y, fmaf(naz, p.z, p.w))));
                p = tile[j+2]; m2 = fminf(m2, fmaf(nax, p.x, fmaf(nay, p.y, fmaf(naz, p.z, p.w))));
                p = tile[j+3]; m3 = fminf(m3, fmaf(nax, p.x, fmaf(nay, p.y, fmaf(naz, p.z, p.w))));
            }
            __syncwarp();
            float m = fminf(fminf(m0, m1), fminf(m2, m3));
            Mq = warp_max_f(m + ha);
        }
        float r = fminf(fminf(m0, m1), fminf(m2, m3)) + ha;   // = dist^2/2
#pragma unroll
        for (int o = 16; o > 0; o >>= 1) r += __shfl_xor_sync(0xffffffffu, r, o);
        if (lane == 0) atomicAdd(&g_acc[job < 8 ? 0 : 1], r);
    } else {
        // ---- pass2: queries = sorted B (16384/job), DB = sorted A (1024, in smem)
        const int b2  = bx - 192;
        const int job = b2 >> 7;
        const int wq  = ((b2 & 127) << 2) + warp;          // 0..511
        const float4* __restrict__ Ap = g_As[job];
        for (int i = tid; i < 1024; i += 128) sdb[i] = Ap[i];
        __syncthreads();

        float4 Q = g_Bs[job][wq * 32 + lane];
        const float nqx = -Q.x, nqy = -Q.y, nqz = -Q.z, hq = Q.w;
        const float xmin = __shfl_sync(0xffffffffu, Q.x, 0);
        const float xmax = __shfl_sync(0xffffffffu, Q.x, 31);
        const float xq   = __shfl_sync(0xffffffffu, Q.x, 16);

        int lo = 0, hi = 1024;
        while (lo < hi) { int mid = (lo + hi) >> 1; if (sdb[mid].x < xq) lo = mid + 1; else hi = mid; }
        int s0 = min(lo >> 5, NTA - 1);

        float m0 = INF, m1 = INF, m2 = INF, m3 = INF, Mq = INF;
        int tr = s0, tl = s0 - 1;
        bool canR = true, canL = (tl >= 0);

        while (canR || canL) {
            float gapR = INF, gapL = INF;
            if (canR) { gapR = fmaxf(sdb[tr * 32].x - xmax, 0.0f);
                        if (0.5f * gapR * gapR >= Mq) canR = false; }
            if (canL) { gapL = fmaxf(xmin - sdb[tl * 32 + 31].x, 0.0f);
                        if (0.5f * gapL * gapL >= Mq) canL = false; }
            int t;
            if (canR && (!canL || gapR <= gapL)) { t = tr++; canR = (tr < NTA); }
            else if (canL)                        { t = tl--; canL = (tl >= 0); }
            else break;

            const float4* base = sdb + t * 32;
#pragma unroll
            for (int j = 0; j < 32; j += 4) {
                float4 p;
                p = base[j+0]; m0 = fminf(m0, fmaf(nqx, p.x, fmaf(nqy, p.y, fmaf(nqz, p.z, p.w))));
                p = base[j+1]; m1 = fminf(m1, fmaf(nqx, p.x, fmaf(nqy, p.y, fmaf(nqz, p.z, p.w))));
                p = base[j+2]; m2 = fminf(m2, fmaf(nqx, p.x, fmaf(nqy, p.y, fmaf(nqz, p.z, p.w))));
                p = base[j+3]; m3 = fminf(m3, fmaf(nqx, p.x, fmaf(nqy, p.y, fmaf(nqz, p.z, p.w))));
            }
            float m = fminf(fminf(m0, m1), fminf(m2, m3));
            Mq = warp_max_f(m + hq);
        }
        float r = fminf(fminf(m0, m1), fminf(m2, m3)) + hq;   // = dist^2/2
#pragma unroll
        for (int o = 16; o > 0; o >>= 1) r += __shfl_xor_sync(0xffffffffu, r, o);
        if (lane == 0) atomicAdd(&g_acc[job < 8 ? 2 : 3], r);
    }
}

// ---------------- finalize: consistency MSE + combine + reset accumulators
__global__ __launch_bounds__(1024)
void k_final(const float* __restrict__ sp,
             const float* __restrict__ tsp,
             const float* __restrict__ M,
             float* __restrict__ out)
{
    int tid = threadIdx.x;
    float e = 0.0f;
#pragma unroll
    for (int k = 0; k < 16; k++) {
        int idx = tid + k * 1024;          // [0, 16384) = T*B*S
        int t  = idx >> 13;
        int bs = idx & 8191;
        const float* p = sp + (size_t)bs * 3;
        float x = p[0], y = p[1], z = p[2];
        const float* m = M + t * 9;
        const float* q = tsp + (size_t)idx * 3;
#pragma unroll
        for (int cc = 0; cc < 3; cc++) {
            float v = fmaf(x, m[cc], fmaf(y, m[3 + cc], z * m[6 + cc]));
            float d = v - q[cc];
            e = fmaf(d, d, e);
        }
    }
    __shared__ float sh[1024];
    sh[tid] = e; __syncthreads();
    for (int s = 512; s > 0; s >>= 1) { if (tid < s) sh[tid] += sh[tid + s]; __syncthreads(); }

    if (tid == 0) {
        float a0 = g_acc[0], a1 = g_acc[1], a2 = g_acc[2], a3 = g_acc[3];
        // values are dist^2/2 sums; mean(dist^2) = 2*sum/cnt; cd = (mean1+mean2)/2
        float cd1 = a0 / 8192.0f  + a2 / 131072.0f;   // 8*1024, 8*16384
        float cd2 = a1 / 16384.0f + a3 / 262144.0f;   // 16*1024, 16*16384
        float consist = sh[0] * (1000.0f / 49152.0f);
        out[0] = (cd1 + cd2) / 3.0f + consist;        // /(T+1)
        g_acc[0] = 0.0f; g_acc[1] = 0.0f; g_acc[2] = 0.0f; g_acc[3] = 0.0f;
    }
}

extern "C" void kernel_launch(void* const* d_in, const int* in_sizes, int n_in,
                              void* d_out, int out_size) {
    const float* gt  = (const float*)d_in[0];   // [8,16384,3]
    const float* sp  = (const float*)d_in[1];   // [8,1024,3]
    const float* tgt = (const float*)d_in[2];   // [2,8,16384,3] -> 16 batches
    const float* tsp = (const float*)d_in[3];   // [2,8,1024,3]  -> 16 batches
    const float* M   = (const float*)d_in[4];   // [2,3,3]
    (void)in_sizes; (void)n_in; (void)out_size;

    cudaFuncSetAttribute(k_sort, cudaFuncAttributeMaxDynamicSharedMemorySize, 131072);
    k_sort <<<48, 1024, 131072>>>(gt, sp, tgt, tsp);
    k_nn   <<<192 + 24 * 128, 128>>>();
    k_final<<<1, 1024>>>(sp, tsp, M, (float*)d_out);
}

// round 6
// speedup vs baseline: 3.2847x; 3.2847x over previous
#include <cuda_runtime.h>

#define SD 1024          // structure points per batch (rows)
#define NP 16384         // gt points per batch (cols)
#define WC 64            // columns per warp
#define WARPS 4
#define COLS_PER_BLOCK (WARPS * WC)   // 256

// scratch (no allocations allowed)
__device__ __align__(16) int g_rowmin[24576]; // 8*1024 (cham1) + 16*1024 (cham2), float bits
__device__ float g_acc[4];                    // [0]=colsum1, [1]=colsum2

__device__ __forceinline__ unsigned long long pack2(float lo, float hi) {
    unsigned long long r;
    asm("mov.b64 %0, {%1, %2};" : "=l"(r) : "f"(lo), "f"(hi));
    return r;
}
__device__ __forceinline__ unsigned long long fma2(unsigned long long a,
                                                   unsigned long long b,
                                                   unsigned long long c) {
    unsigned long long d;
    asm("fma.rn.f32x2 %0, %1, %2, %3;" : "=l"(d) : "l"(a), "l"(b), "l"(c));
    return d;
}
__device__ __forceinline__ unsigned long long add2(unsigned long long a,
                                                   unsigned long long b) {
    unsigned long long d;
    asm("add.rn.f32x2 %0, %1, %2;" : "=l"(d) : "l"(a), "l"(b));
    return d;
}
__device__ __forceinline__ void unpack2(float& lo, float& hi, unsigned long long v) {
    asm("mov.b64 {%0, %1}, %2;" : "=f"(lo), "=f"(hi) : "l"(v));
}

__global__ __launch_bounds__(1024)
void k_init() {
    int i = blockIdx.x * 1024 + threadIdx.x;
    g_rowmin[i] = 0x7f800000;
    if (i < 4) g_acc[i] = 0.0f;
}

__global__ void k_nop() {}   // launch-sequence pad so ncu -s 5 hits k_chamfer

// merged chamfer: blockIdx.y in [0,24): y<16 -> (tsp,tgt) job, y>=16 -> (sp,gt) job
__global__ __launch_bounds__(WARPS * 32, 3)
void k_chamfer(const float* __restrict__ sp,  const float* __restrict__ gt,
               const float* __restrict__ tsp, const float* __restrict__ tgt)
{
    __shared__ ulonglong2 tile2[WARPS][32][2];   // duplicated packs {xx,yy},{zz,hh}

    const int y    = blockIdx.y;
    const int tid  = threadIdx.x;
    const int lane = tid & 31;
    const int warp = tid >> 5;
    const float INF = __int_as_float(0x7f800000);

    const float* pa; const float* pb; int rowoff, acc_idx;
    if (y < 16) { pa = tsp + (size_t)y * SD * 3;       pb = tgt + (size_t)y * NP * 3;
                  rowoff = 8192 + y * SD;              acc_idx = 1; }
    else        { int b = y - 16;
                  pa = sp + (size_t)b * SD * 3;        pb = gt + (size_t)b * NP * 3;
                  rowoff = b * SD;                     acc_idx = 0; }

    // ---- all 1024 rows of this batch in this warp's registers ----
    // lane l holds rows { i*32 + l }, packed in pairs (2i, 2i+1)
    unsigned long long nax2[16], nay2[16], naz2[16], ha2[16];
    float rl[16], rh[16];
#pragma unroll
    for (int i = 0; i < 16; i++) {
        int r0 = (2 * i) * 32 + lane;
        int r1 = r0 + 32;
        float x0 = pa[r0*3+0], y0 = pa[r0*3+1], z0 = pa[r0*3+2];
        float x1 = pa[r1*3+0], y1 = pa[r1*3+1], z1 = pa[r1*3+2];
        nax2[i] = pack2(-x0, -x1);
        nay2[i] = pack2(-y0, -y1);
        naz2[i] = pack2(-z0, -z1);
        ha2[i]  = pack2(0.5f * (x0*x0 + y0*y0 + z0*z0),
                        0.5f * (x1*x1 + y1*y1 + z1*z1));
        rl[i] = INF; rh[i] = INF;
    }

    const int cbase = blockIdx.x * COLS_PER_BLOCK + warp * WC;

    // prefetch first tile's column
    int c = cbase + lane;
    float cx = pb[c*3+0], cy = pb[c*3+1], cz = pb[c*3+2];

    float csum = 0.0f;

#pragma unroll
    for (int t = 0; t < WC / 32; t++) {
        {   // stage duplicated packs: 32 B per column
            float hb = 0.5f * (cx*cx + cy*cy + cz*cz);
            ulonglong2 v0, v1;
            v0.x = pack2(cx, cx); v0.y = pack2(cy, cy);
            v1.x = pack2(cz, cz); v1.y = pack2(hb, hb);
            tile2[warp][lane][0] = v0;
            tile2[warp][lane][1] = v1;
        }
        __syncwarp();
        if (t + 1 < WC / 32) {               // prefetch next tile from gmem
            int cn = cbase + (t + 1) * 32 + lane;
            cx = pb[cn*3+0]; cy = pb[cn*3+1]; cz = pb[cn*3+2];
        }

        // systolic: at step j, lane l owns the accumulator for column (j+l)&31.
        // Column data for the NEXT step is LDS-prefetched one step ahead.
        float acc = INF;
        ulonglong2 A  = tile2[warp][lane][0];
        ulonglong2 Bv = tile2[warp][lane][1];
#pragma unroll 2
        for (int j = 0; j < 32; j++) {
            ulonglong2 An, Bn;
            if (j < 31) {
                int idx2 = (j + 1 + lane) & 31;
                An = tile2[warp][idx2][0];
                Bn = tile2[warp][idx2][1];
            }
            // two independent local chains (even/odd i) -> short dep chains
            float la = INF, lb = INF;
#pragma unroll
            for (int i = 0; i < 16; i++) {
                unsigned long long q =
                    add2(fma2(nax2[i], A.x,
                         fma2(nay2[i], A.y,
                         fma2(naz2[i], Bv.x, ha2[i]))), Bv.y);
                float lo, hi; unpack2(lo, hi, q);
                rl[i] = fminf(rl[i], lo);
                rh[i] = fminf(rh[i], hi);
                float m = fminf(lo, hi);
                if (i & 1) lb = fminf(lb, m); else la = fminf(la, m);
            }
            acc = fminf(acc, fminf(la, lb));
            acc = __shfl_sync(0xffffffffu, acc, (lane + 1) & 31);
            A = An; Bv = Bn;
        }
        // lane l now holds the complete (1024-row) min of column l of this tile
        csum += acc;
        __syncwarp();
    }

    // per-warp sum of column mins -> one atomicAdd
#pragma unroll
    for (int o = 16; o > 0; o >>= 1)
        csum += __shfl_xor_sync(0xffffffffu, csum, o);
    if (lane == 0) atomicAdd(&g_acc[acc_idx], csum);

    // partial row-mins -> global (non-negative floats: int order preserved)
    int* rm = g_rowmin + rowoff;
#pragma unroll
    for (int i = 0; i < 16; i++) {
        int r0 = (2 * i) * 32 + lane;
        atomicMin(&rm[r0],      __float_as_int(rl[i]));
        atomicMin(&rm[r0 + 32], __float_as_int(rh[i]));
    }
}

// finalize: row-min sums (int4 loads) + consistency MSE + combine
__global__ __launch_bounds__(1024)
void k_final(const float* __restrict__ sp,
             const float* __restrict__ tsp,
             const float* __restrict__ M,
             float* __restrict__ out)
{
    int tid = threadIdx.x;

    // consistency: tmp[t,b,s,e] = sum_d sp[b,s,d]*M[t,d,e]; SSE vs tsp
    float e = 0.0f;
#pragma unroll
    for (int k = 0; k < 16; k++) {
        int idx = tid + k * 1024;          // [0, 16384) = T*B*S
        int t  = idx >> 13;
        int bs = idx & 8191;
        const float* p = sp + (size_t)bs * 3;
        float x = p[0], y = p[1], z = p[2];
        const float* m = M + t * 9;
        const float* q = tsp + (size_t)idx * 3;
#pragma unroll
        for (int cc = 0; cc < 3; cc++) {
            float v = fmaf(x, m[cc], fmaf(y, m[3 + cc], z * m[6 + cc]));
            float d = v - q[cc];
            e = fmaf(d, d, e);
        }
    }

    // row-min sums, vectorized: 24576 ints = 6144 int4 (first 2048 = chamfer1)
    const int4* rm4 = (const int4*)g_rowmin;
    float a1 = 0.0f, a2 = 0.0f;
#pragma unroll
    for (int k = 0; k < 6; k++) {
        int i = tid + k * 1024;
        int4 v = rm4[i];
        float s = __int_as_float(v.x) + __int_as_float(v.y)
                + __int_as_float(v.z) + __int_as_float(v.w);
        if (i < 2048) a1 += s; else a2 += s;
    }

    __shared__ float sh[1024];
    sh[tid] = a1; __syncthreads();
    for (int s = 512; s > 0; s >>= 1) { if (tid < s) sh[tid] += sh[tid + s]; __syncthreads(); }
    float rs1 = sh[0]; __syncthreads();
    sh[tid] = a2; __syncthreads();
    for (int s = 512; s > 0; s >>= 1) { if (tid < s) sh[tid] += sh[tid + s]; __syncthreads(); }
    float rs2 = sh[0]; __syncthreads();
    sh[tid] = e; __syncthreads();
    for (int s = 512; s > 0; s >>= 1) { if (tid < s) sh[tid] += sh[tid + s]; __syncthreads(); }

    if (tid == 0) {
        // t-space = dist/2; cd = mean_rowmin_t + mean_colmin_t
        float cd1 = rs1 / 8192.0f  + g_acc[0] / 131072.0f;   // 8*1024, 8*16384
        float cd2 = rs2 / 16384.0f + g_acc[1] / 262144.0f;   // 16*1024, 16*16384
        float consist = sh[0] * (1000.0f / 49152.0f);        // mean over T*B*S*D
        out[0] = (cd1 + cd2) / 3.0f + consist;               // /(T+1)
    }
}

extern "C" void kernel_launch(void* const* d_in, const int* in_sizes, int n_in,
                              void* d_out, int out_size) {
    const float* gt  = (const float*)d_in[0];   // [8,16384,3]
    const float* sp  = (const float*)d_in[1];   // [8,1024,3]
    const float* tgt = (const float*)d_in[2];   // [2,8,16384,3] -> 16 batches
    const float* tsp = (const float*)d_in[3];   // [2,8,1024,3]  -> 16 batches
    const float* M   = (const float*)d_in[4];   // [2,3,3]
    (void)in_sizes; (void)n_in; (void)out_size;

    k_init<<<24, 1024>>>();
    k_chamfer<<<dim3(NP / COLS_PER_BLOCK, 24), WARPS * 32>>>(sp, gt, tsp, tgt);
    k_final<<<1, 1024>>>(sp, tsp, M, (float*)d_out);
    k_nop<<<1, 1>>>();   // pads launch sequence: ncu -s 5 lands on iter-2 k_chamfer
}

// round 7
// speedup vs baseline: 4.0663x; 1.2380x over previous
#include <cuda_runtime.h>

#define SD 1024          // structure points per batch (rows)
#define NP 16384         // gt points per batch (cols)
#define WC 64            // columns per warp-pair
#define WARPS 8          // 4 column-groups x 2 row-halves
#define COLS_PER_BLOCK (4 * WC)   // 256

// scratch (no allocations allowed)
__device__ __align__(16) int g_rowmin[24576]; // 8*1024 (cham1) + 16*1024 (cham2), float bits
__device__ float g_acc[4];                    // [0]=colsum1, [1]=colsum2

__device__ __forceinline__ unsigned long long pack2(float lo, float hi) {
    unsigned long long r;
    asm("mov.b64 %0, {%1, %2};" : "=l"(r) : "f"(lo), "f"(hi));
    return r;
}

// two pairs: q = (nax,nay,naz).(p) + ha + hb (packed f32x2);
// update the two row-mins and the traveling column accumulator.
__device__ __forceinline__ void pair_step(
    unsigned long long nax2, unsigned long long nay2, unsigned long long naz2,
    unsigned long long ha2,
    unsigned long long px2, unsigned long long py2, unsigned long long pz2,
    unsigned long long hb2,
    float& rlo, float& rhi, float& acc)
{
    asm("{\n\t"
        ".reg .b64 q;\n\t"
        ".reg .f32 lo, hi;\n\t"
        "fma.rn.f32x2 q, %5, %9, %6;\n\t"   // naz2*pz2 + ha2
        "fma.rn.f32x2 q, %4, %8, q;\n\t"    // + nay2*py2
        "fma.rn.f32x2 q, %3, %7, q;\n\t"    // + nax2*px2
        "add.rn.f32x2 q, q, %10;\n\t"       // + hb2
        "mov.b64 {lo, hi}, q;\n\t"
        "min.f32 %0, %0, lo;\n\t"
        "min.f32 %1, %1, hi;\n\t"
        "min.f32 %2, %2, lo;\n\t"
        "min.f32 %2, %2, hi;\n\t"
        "}"
        : "+f"(rlo), "+f"(rhi), "+f"(acc)
        : "l"(nax2), "l"(nay2), "l"(naz2), "l"(ha2),
          "l"(px2), "l"(py2), "l"(pz2), "l"(hb2));
}

__global__ __launch_bounds__(1024)
void k_init() {
    int i = blockIdx.x * 1024 + threadIdx.x;
    g_rowmin[i] = 0x7f800000;
    if (i < 4) g_acc[i] = 0.0f;
}

// merged chamfer: blockIdx.y in [0,24): y<16 -> (tsp,tgt) job, y>=16 -> (sp,gt) job
// warps 0-3: rows [0,512) of column-group (warp); warps 4-7: rows [512,1024) of group (warp-4)
__global__ __launch_bounds__(WARPS * 32)
void k_chamfer(const float* __restrict__ sp,  const float* __restrict__ gt,
               const float* __restrict__ tsp, const float* __restrict__ tgt)
{
    __shared__ ulonglong2 tile2[WARPS][32][2];   // duplicated packs {xx,yy},{zz,hh}
    __shared__ float wmin[WARPS][32];

    const int y    = blockIdx.y;
    const int tid  = threadIdx.x;
    const int lane = tid & 31;
    const int warp = tid >> 5;
    const int grp  = warp & 3;          // column group
    const int half = warp >> 2;         // row half
    const float INF = __int_as_float(0x7f800000);

    const float* pa; const float* pb; int rowoff, acc_idx;
    if (y < 16) { pa = tsp + (size_t)y * SD * 3;       pb = tgt + (size_t)y * NP * 3;
                  rowoff = 8192 + y * SD;              acc_idx = 1; }
    else        { int b = y - 16;
                  pa = sp + (size_t)b * SD * 3;        pb = gt + (size_t)b * NP * 3;
                  rowoff = b * SD;                     acc_idx = 0; }

    // ---- this warp's 512 rows in registers ----
    // lane l holds rows { rowbase + i*32 + l : i in [0,16) }, packed pairs (2i,2i+1)
    const int rowbase = half * 512;
    unsigned long long nax2[8], nay2[8], naz2[8], ha2[8];
    float rl[8], rh[8];
#pragma unroll
    for (int i = 0; i < 8; i++) {
        int r0 = rowbase + (2 * i) * 32 + lane;
        int r1 = r0 + 32;
        float x0 = pa[r0*3+0], y0 = pa[r0*3+1], z0 = pa[r0*3+2];
        float x1 = pa[r1*3+0], y1 = pa[r1*3+1], z1 = pa[r1*3+2];
        nax2[i] = pack2(-x0, -x1);
        nay2[i] = pack2(-y0, -y1);
        naz2[i] = pack2(-z0, -z1);
        ha2[i]  = pack2(0.5f * (x0*x0 + y0*y0 + z0*z0),
                        0.5f * (x1*x1 + y1*y1 + z1*z1));
        rl[i] = INF; rh[i] = INF;
    }

    const int cbase = blockIdx.x * COLS_PER_BLOCK + grp * WC;

    // prefetch first tile's column
    int c = cbase + lane;
    float cx = pb[c*3+0], cy = pb[c*3+1], cz = pb[c*3+2];

    float csum = 0.0f;

#pragma unroll
    for (int t = 0; t < WC / 32; t++) {
        {   // stage duplicated packs: 32 B per column (own tile, warp-private)
            float hb = 0.5f * (cx*cx + cy*cy + cz*cz);
            ulonglong2 v0, v1;
            v0.x = pack2(cx, cx); v0.y = pack2(cy, cy);
            v1.x = pack2(cz, cz); v1.y = pack2(hb, hb);
            tile2[warp][lane][0] = v0;
            tile2[warp][lane][1] = v1;
        }
        __syncwarp();
        if (t + 1 < WC / 32) {               // prefetch next tile from gmem
            int cn = cbase + (t + 1) * 32 + lane;
            cx = pb[cn*3+0]; cy = pb[cn*3+1]; cz = pb[cn*3+2];
        }

        // systolic: at step j, lane l owns the accumulator for column (j+l)&31,
        // mins its 512 rows into it, passes it on.
        float acc = INF;
#pragma unroll 2
        for (int j = 0; j < 32; j++) {
            int idx = (j + lane) & 31;
            ulonglong2 A  = tile2[warp][idx][0];
            ulonglong2 Bv = tile2[warp][idx][1];
#pragma unroll
            for (int i = 0; i < 8; i++)
                pair_step(nax2[i], nay2[i], naz2[i], ha2[i],
                          A.x, A.y, Bv.x, Bv.y, rl[i], rh[i], acc);
            acc = __shfl_sync(0xffffffffu, acc, (lane + 1) & 31);
        }
        // lane l: min of column (cbase + t*32 + l) over this warp's 512 rows.
        // combine the two row-halves through shared.
        wmin[warp][lane] = acc;
        __syncthreads();
        if (half == 0)
            csum += fminf(acc, wmin[warp + 4][lane]);
        __syncthreads();
    }

    // per-warp sum of column mins -> one atomicAdd (halves 0 only)
    if (half == 0) {
#pragma unroll
        for (int o = 16; o > 0; o >>= 1)
            csum += __shfl_xor_sync(0xffffffffu, csum, o);
        if (lane == 0) atomicAdd(&g_acc[acc_idx], csum);
    }

    // partial row-mins -> global (non-negative floats: int order preserved)
    int* rm = g_rowmin + rowoff + rowbase;
#pragma unroll
    for (int i = 0; i < 8; i++) {
        int r0 = (2 * i) * 32 + lane;
        atomicMin(&rm[r0],      __float_as_int(rl[i]));
        atomicMin(&rm[r0 + 32], __float_as_int(rh[i]));
    }
}

// finalize: row-min sums (int4 loads) + consistency MSE + combine
__global__ __launch_bounds__(1024)
void k_final(const float* __restrict__ sp,
             const float* __restrict__ tsp,
             const float* __restrict__ M,
             float* __restrict__ out)
{
    int tid = threadIdx.x;

    // consistency: tmp[t,b,s,e] = sum_d sp[b,s,d]*M[t,d,e]; SSE vs tsp
    float e = 0.0f;
#pragma unroll
    for (int k = 0; k < 16; k++) {
        int idx = tid + k * 1024;          // [0, 16384) = T*B*S
        int t  = idx >> 13;
        int bs = idx & 8191;
        const float* p = sp + (size_t)bs * 3;
        float x = p[0], y = p[1], z = p[2];
        const float* m = M + t * 9;
        const float* q = tsp + (size_t)idx * 3;
#pragma unroll
        for (int cc = 0; cc < 3; cc++) {
            float v = fmaf(x, m[cc], fmaf(y, m[3 + cc], z * m[6 + cc]));
            float d = v - q[cc];
            e = fmaf(d, d, e);
        }
    }

    // row-min sums, vectorized: 24576 ints = 6144 int4 (first 2048 = chamfer1)
    const int4* rm4 = (const int4*)g_rowmin;
    float a1 = 0.0f, a2 = 0.0f;
#pragma unroll
    for (int k = 0; k < 6; k++) {
        int i = tid + k * 1024;
        int4 v = rm4[i];
        float s = __int_as_float(v.x) + __int_as_float(v.y)
                + __int_as_float(v.z) + __int_as_float(v.w);
        if (i < 2048) a1 += s; else a2 += s;
    }

    __shared__ float sh[1024];
    sh[tid] = a1; __syncthreads();
    for (int s = 512; s > 0; s >>= 1) { if (tid < s) sh[tid] += sh[tid + s]; __syncthreads(); }
    float rs1 = sh[0]; __syncthreads();
    sh[tid] = a2; __syncthreads();
    for (int s = 512; s > 0; s >>= 1) { if (tid < s) sh[tid] += sh[tid + s]; __syncthreads(); }
    float rs2 = sh[0]; __syncthreads();
    sh[tid] = e; __syncthreads();
    for (int s = 512; s > 0; s >>= 1) { if (tid < s) sh[tid] += sh[tid + s]; __syncthreads(); }

    if (tid == 0) {
        // t-space = dist/2; cd = mean_rowmin_t + mean_colmin_t
        float cd1 = rs1 / 8192.0f  + g_acc[0] / 131072.0f;   // 8*1024, 8*16384
        float cd2 = rs2 / 16384.0f + g_acc[1] / 262144.0f;   // 16*1024, 16*16384
        float consist = sh[0] * (1000.0f / 49152.0f);        // mean over T*B*S*D
        out[0] = (cd1 + cd2) / 3.0f + consist;               // /(T+1)
    }
}

extern "C" void kernel_launch(void* const* d_in, const int* in_sizes, int n_in,
                              void* d_out, int out_size) {
    const float* gt  = (const float*)d_in[0];   // [8,16384,3]
    const float* sp  = (const float*)d_in[1];   // [8,1024,3]
    const float* tgt = (const float*)d_in[2];   // [2,8,16384,3] -> 16 batches
    const float* tsp = (const float*)d_in[3];   // [2,8,1024,3]  -> 16 batches
    const float* M   = (const float*)d_in[4];   // [2,3,3]
    (void)in_sizes; (void)n_in; (void)out_size;

    k_init<<<24, 1024>>>();
    k_chamfer<<<dim3(NP / COLS_PER_BLOCK, 24), WARPS * 32>>>(sp, gt, tsp, tgt);
    k_final<<<1, 1024>>>(sp, tsp, M, (float*)d_out);
}